// round 1
// baseline (speedup 1.0000x reference)
#include <cuda_runtime.h>
#include <cstdint>

// COO SpMM: out[rows[e]] += vals[e] * x[cols[e]]   (DIM = 32)
//
// Work decomposition: one thread per (edge, quarter-row) pair.
//   e = idx >> 3, q = idx & 7
// Lanes 8k..8k+7 of a warp cover one edge's full 32-dim row as 8 contiguous
// float4s -> the gather from x and the scatter-reduce to out are each a
// single contiguous 128B segment per edge.
//
// Scatter uses red.global.add.v4.f32 (sm_90+): fire-and-forget 128-bit
// reduction handled at the LTS atomic ALUs; no return value, no latency
// exposure in the warp.

static constexpr int DIM  = 32;
static constexpr int QPE  = DIM / 4;   // float4 quarters per edge = 8
static constexpr int TPB  = 256;

__global__ void __launch_bounds__(TPB)
lightgcn_spmm_kernel(const int*    __restrict__ rows,
                     const int*    __restrict__ cols,
                     const float*  __restrict__ vals,
                     const float4* __restrict__ x4,      // [N_NODES * 8]
                     float*        __restrict__ out,     // [N_NODES * 32]
                     int n_edges)
{
    int idx   = blockIdx.x * TPB + threadIdx.x;
    int total = n_edges * QPE;
    if (idx >= total) return;

    int e = idx >> 3;
    int q = idx & 7;

    // 8 lanes of the same edge read identical row/col/val words ->
    // single sector per warp-quad, L1 broadcast.
    int   row = rows[e];
    int   col = cols[e];
    float v   = vals[e];

    float4 xv = __ldg(&x4[col * QPE + q]);

    float4 m;
    m.x = xv.x * v;
    m.y = xv.y * v;
    m.z = xv.z * v;
    m.w = xv.w * v;

    float* dst = out + ((size_t)row * DIM + q * 4);
    asm volatile(
        "red.global.add.v4.f32 [%0], {%1, %2, %3, %4};"
        :: "l"(dst), "f"(m.x), "f"(m.y), "f"(m.z), "f"(m.w)
        : "memory");
}

extern "C" void kernel_launch(void* const* d_in, const int* in_sizes, int n_in,
                              void* d_out, int out_size)
{
    const int*    rows = (const int*)   d_in[0];  // A_rows [E]
    const int*    cols = (const int*)   d_in[1];  // A_cols [E]
    const float*  vals = (const float*) d_in[2];  // A_vals [E]
    const float4* x4   = (const float4*)d_in[3];  // x [N, 32] as float4[N*8]
    float*        out  = (float*)d_out;

    int n_edges = in_sizes[0];

    // Output is poisoned to 0xAA by the harness; reductions need zeros.
    cudaMemsetAsync(d_out, 0, (size_t)out_size * sizeof(float), 0);

    int total  = n_edges * QPE;
    int blocks = (total + TPB - 1) / TPB;
    lightgcn_spmm_kernel<<<blocks, TPB>>>(rows, cols, vals, x4, out, n_edges);
}

// round 3
// speedup vs baseline: 1.0536x; 1.0536x over previous
#include <cuda_runtime.h>
#include <cstdint>

// COO SpMM: out[rows[e]] += vals[e] * x[cols[e]]   (DIM = 32)
//
// Layout: each warp covers 16 edges, 4 edges per thread (ILP=4).
//   lane: q = lane & 7 (float4 quarter), sub = lane >> 3 (0..3)
//   thread's edges: e_i = warpBase*16 + i*4 + sub, i in 0..3
// Lanes 0..7 of any edge are adjacent -> the x-gather and the RED scatter
// are each one contiguous 128B segment per edge (minimal L1 wavefronts).
// The 16 edge indices per warp span 64B -> 1 wavefront per scalar array.
//
// 4 independent (idx load -> x load -> FMA -> RED) chains per thread hide
// the ~250-cycle L2-hit latency.

static constexpr int DIM = 32;
static constexpr int QPE = DIM / 4;   // 8 float4 quarters per edge
static constexpr int TPB = 256;
static constexpr int EPT = 4;         // edges per thread
static constexpr int EPW = 16;        // edges per warp

__device__ __forceinline__ void red_add_v4(float* dst, float4 m) {
    asm volatile(
        "red.global.add.v4.f32 [%0], {%1, %2, %3, %4};"
        :: "l"(dst), "f"(m.x), "f"(m.y), "f"(m.z), "f"(m.w)
        : "memory");
}

__global__ void __launch_bounds__(TPB)
lightgcn_spmm_kernel(const int*    __restrict__ rows,
                     const int*    __restrict__ cols,
                     const float*  __restrict__ vals,
                     const float4* __restrict__ x4,      // [N_NODES * 8]
                     float*        __restrict__ out,     // [N_NODES * 32]
                     int n_edges)
{
    int tid  = blockIdx.x * TPB + threadIdx.x;
    int warp = tid >> 5;
    int lane = threadIdx.x & 31;
    int q    = lane & 7;
    int sub  = lane >> 3;

    float* outq = out + q * 4;          // hoist quarter offset
    int base = warp * EPW + sub;        // edges: base, base+4, base+8, base+12

    if (base + 3 * 4 < n_edges) {
        // ---- fast path: all 4 edges valid ----
        int   r[EPT], c[EPT];
        float v[EPT];
        #pragma unroll
        for (int i = 0; i < EPT; i++) {
            int e = base + i * 4;
            r[i] = __ldg(&rows[e]);
            c[i] = __ldg(&cols[e]);
            v[i] = __ldg(&vals[e]);
        }

        float4 xv[EPT];
        #pragma unroll
        for (int i = 0; i < EPT; i++)
            xv[i] = __ldg(&x4[c[i] * QPE + q]);

        #pragma unroll
        for (int i = 0; i < EPT; i++) {
            float4 m;
            m.x = xv[i].x * v[i];
            m.y = xv[i].y * v[i];
            m.z = xv[i].z * v[i];
            m.w = xv[i].w * v[i];
            red_add_v4(outq + (size_t)r[i] * DIM, m);
        }
    } else {
        // ---- tail path ----
        #pragma unroll
        for (int i = 0; i < EPT; i++) {
            int e = base + i * 4;
            if (e < n_edges) {
                int   rr = __ldg(&rows[e]);
                int   cc = __ldg(&cols[e]);
                float vv = __ldg(&vals[e]);
                float4 xv = __ldg(&x4[cc * QPE + q]);
                float4 m;
                m.x = xv.x * vv;
                m.y = xv.y * vv;
                m.z = xv.z * vv;
                m.w = xv.w * vv;
                red_add_v4(outq + (size_t)rr * DIM, m);
            }
        }
    }
}

extern "C" void kernel_launch(void* const* d_in, const int* in_sizes, int n_in,
                              void* d_out, int out_size)
{
    const int*    rows = (const int*)   d_in[0];  // A_rows [E]
    const int*    cols = (const int*)   d_in[1];  // A_cols [E]
    const float*  vals = (const float*) d_in[2];  // A_vals [E]
    const float4* x4   = (const float4*)d_in[3];  // x [N, 32] as float4[N*8]
    float*        out  = (float*)d_out;

    int n_edges = in_sizes[0];

    // Output is poisoned to 0xAA by the harness; reductions need zeros.
    cudaMemsetAsync(d_out, 0, (size_t)out_size * sizeof(float), 0);

    int n_warps  = (n_edges + EPW - 1) / EPW;
    int n_thread = n_warps * 32;
    int blocks   = (n_thread + TPB - 1) / TPB;
    lightgcn_spmm_kernel<<<blocks, TPB>>>(rows, cols, vals, x4, out, n_edges);
}

// round 4
// speedup vs baseline: 1.0934x; 1.0378x over previous
#include <cuda_runtime.h>
#include <cstdint>

// COO SpMM: out[rows[e]] += vals[e] * x[cols[e]]   (DIM = 32)
//
// Layout: each warp covers 16 edges, 4 CONSECUTIVE edges per thread-octet.
//   lane: q = lane & 7 (float4 quarter of the 32-dim row), sub = lane >> 3
//   octet sub's edges: e = warpBase*16 + sub*4 + {0,1,2,3}
//
// Index/weight loads are one int4/int4/float4 per thread (16B aligned),
// so each scalar array costs 1 L1 request per warp instead of 4.
// Per edge, the x-gather and the RED scatter are each one contiguous
// 128B segment across the octet's 8 lanes (1 L1 wavefront each).
//
// Scatter uses red.global.add.v4.f32: fire-and-forget 128-bit reduction
// at the LTS atomic ALUs, no latency exposure.

static constexpr int DIM = 32;
static constexpr int QPE = DIM / 4;   // 8 float4 quarters per edge
static constexpr int TPB = 256;
static constexpr int EPT = 4;         // edges per thread
static constexpr int EPW = 16;        // edges per warp

__device__ __forceinline__ void red_add_v4(float* dst, float4 m) {
    asm volatile(
        "red.global.add.v4.f32 [%0], {%1, %2, %3, %4};"
        :: "l"(dst), "f"(m.x), "f"(m.y), "f"(m.z), "f"(m.w)
        : "memory");
}

__global__ void __launch_bounds__(TPB)
lightgcn_spmm_kernel(const int4*   __restrict__ rows4,
                     const int4*   __restrict__ cols4,
                     const float4* __restrict__ vals4,
                     const float4* __restrict__ x4,      // [N_NODES * 8]
                     float*        __restrict__ out,     // [N_NODES * 32]
                     int n_edges)
{
    int tid  = blockIdx.x * TPB + threadIdx.x;
    int warp = tid >> 5;
    int lane = threadIdx.x & 31;
    int q    = lane & 7;
    int sub  = lane >> 3;

    float* outq = out + q * 4;                 // hoist quarter offset
    int    g    = warp * (EPW / 4) + sub;      // group of 4 consecutive edges
    int    base = g * 4;

    if (base + 3 < n_edges) {
        // ---- fast path: whole int4 group valid ----
        int4   r = __ldg(&rows4[g]);
        int4   c = __ldg(&cols4[g]);
        float4 v = __ldg(&vals4[g]);

        int   ra[EPT] = { r.x, r.y, r.z, r.w };
        int   ca[EPT] = { c.x, c.y, c.z, c.w };
        float va[EPT] = { v.x, v.y, v.z, v.w };

        float4 xv[EPT];
        #pragma unroll
        for (int i = 0; i < EPT; i++)
            xv[i] = __ldg(&x4[ca[i] * QPE + q]);

        #pragma unroll
        for (int i = 0; i < EPT; i++) {
            float4 m;
            m.x = xv[i].x * va[i];
            m.y = xv[i].y * va[i];
            m.z = xv[i].z * va[i];
            m.w = xv[i].w * va[i];
            red_add_v4(outq + (size_t)ra[i] * DIM, m);
        }
    } else {
        // ---- tail path: per-edge scalar ----
        const int*   rows = (const int*)  rows4;
        const int*   cols = (const int*)  cols4;
        const float* vals = (const float*)vals4;
        #pragma unroll
        for (int i = 0; i < EPT; i++) {
            int e = base + i;
            if (e < n_edges) {
                int   rr = __ldg(&rows[e]);
                int   cc = __ldg(&cols[e]);
                float vv = __ldg(&vals[e]);
                float4 xv = __ldg(&x4[cc * QPE + q]);
                float4 m;
                m.x = xv.x * vv;
                m.y = xv.y * vv;
                m.z = xv.z * vv;
                m.w = xv.w * vv;
                red_add_v4(outq + (size_t)rr * DIM, m);
            }
        }
    }
}

extern "C" void kernel_launch(void* const* d_in, const int* in_sizes, int n_in,
                              void* d_out, int out_size)
{
    const int4*   rows4 = (const int4*)  d_in[0];  // A_rows [E]
    const int4*   cols4 = (const int4*)  d_in[1];  // A_cols [E]
    const float4* vals4 = (const float4*)d_in[2];  // A_vals [E]
    const float4* x4    = (const float4*)d_in[3];  // x [N, 32] as float4[N*8]
    float*        out   = (float*)d_out;

    int n_edges = in_sizes[0];

    // Output is poisoned to 0xAA by the harness; reductions need zeros.
    cudaMemsetAsync(d_out, 0, (size_t)out_size * sizeof(float), 0);

    int n_warps  = (n_edges + EPW - 1) / EPW;
    int n_thread = n_warps * 32;
    int blocks   = (n_thread + TPB - 1) / TPB;
    lightgcn_spmm_kernel<<<blocks, TPB>>>(rows4, cols4, vals4, x4, out, n_edges);
}